// round 1
// baseline (speedup 1.0000x reference)
#include <cuda_runtime.h>
#include <math.h>

// Problem constants
#define PB   8
#define PN   1024
#define PD   768
#define PH   12
#define PHD  64
#define PM   (PB * PN)        // 8192
#define PQKV (3 * PD)         // 2304
#define PSCALE 0.125f         // 64^-0.5

// Scratch (allocation-free rule: __device__ globals)
__device__ float g_q[PB * PH * PN * PHD];     // [B,H,N,64]
__device__ float g_k[PB * PH * PN * PHD];
__device__ float g_v[PB * PH * PN * PHD];
__device__ float g_ctx[(size_t)PM * PD];      // [B*N, D]

// ---------------------------------------------------------------------------
// Tiled SGEMM: C[M,NC] = A[M,K] @ W[K,NC] + bias
// MODE 0: A = x, epilogue scatters into g_q/g_k/g_v ([B,H,N,64] layout)
// MODE 1: A = g_ctx, epilogue writes C (d_out)
// Tile: 128x128x16, 256 threads, 8x8 per thread (4+4 split microtiles)
// ---------------------------------------------------------------------------
#define BM 128
#define BN 128
#define BK 16

template <int MODE>
__global__ __launch_bounds__(256, 2) void gemm_kernel(
    const float* __restrict__ Ain, const float* __restrict__ W,
    const float* __restrict__ bias, float* __restrict__ C,
    int K, int NC)
{
    __shared__ float As[BK][BM];   // stored transposed
    __shared__ float Bs[BK][BN];

    const float* A = (MODE == 1) ? (const float*)g_ctx : Ain;

    const int m0 = blockIdx.y * BM;
    const int n0 = blockIdx.x * BN;
    const int t  = threadIdx.x;
    const int tx = t & 15;         // 0..15 -> column group
    const int ty = t >> 4;         // 0..15 -> row group

    float acc[8][8];
#pragma unroll
    for (int i = 0; i < 8; i++)
#pragma unroll
        for (int j = 0; j < 8; j++) acc[i][j] = 0.f;

    for (int k0 = 0; k0 < K; k0 += BK) {
        // Load A tile (128 rows x 16 k), store transposed. 512 float4s.
#pragma unroll
        for (int s = 0; s < 2; s++) {
            int idx = t + s * 256;          // float4 index
            int row = idx >> 2;             // 0..127
            int kc  = (idx & 3) * 4;        // 0,4,8,12
            float4 v = *(const float4*)(A + (size_t)(m0 + row) * K + k0 + kc);
            As[kc + 0][row] = v.x;
            As[kc + 1][row] = v.y;
            As[kc + 2][row] = v.z;
            As[kc + 3][row] = v.w;
        }
        // Load B tile (16 k x 128 cols). 512 float4s.
#pragma unroll
        for (int s = 0; s < 2; s++) {
            int idx = t + s * 256;
            int row = idx >> 5;             // 0..15
            int cc  = (idx & 31) * 4;       // 0..124
            *(float4*)&Bs[row][cc] =
                *(const float4*)(W + (size_t)(k0 + row) * NC + n0 + cc);
        }
        __syncthreads();

#pragma unroll
        for (int k = 0; k < BK; k++) {
            float a[8], b[8];
            *(float4*)&a[0] = *(float4*)&As[k][ty * 4];
            *(float4*)&a[4] = *(float4*)&As[k][64 + ty * 4];
            *(float4*)&b[0] = *(float4*)&Bs[k][tx * 4];
            *(float4*)&b[4] = *(float4*)&Bs[k][64 + tx * 4];
#pragma unroll
            for (int i = 0; i < 8; i++)
#pragma unroll
                for (int j = 0; j < 8; j++)
                    acc[i][j] = fmaf(a[i], b[j], acc[i][j]);
        }
        __syncthreads();
    }

    // Epilogue
#pragma unroll
    for (int i = 0; i < 8; i++) {
        int rm = m0 + ((i < 4) ? (ty * 4 + i) : (64 + ty * 4 + i - 4));
#pragma unroll
        for (int j = 0; j < 8; j++) {
            int cn = n0 + ((j < 4) ? (tx * 4 + j) : (64 + tx * 4 + j - 4));
            float v = acc[i][j] + bias[cn];
            if (MODE == 0) {
                int which = cn / PD;              // 0=q 1=k 2=v
                int d  = cn - which * PD;
                int h  = d >> 6;
                int hd = d & 63;
                int bb = rm >> 10;
                int nn = rm & 1023;
                float* dst = (which == 0) ? g_q : ((which == 1) ? g_k : g_v);
                dst[(((size_t)(bb * PH + h)) * PN + nn) * PHD + hd] = v;
            } else {
                C[(size_t)rm * NC + cn] = v;
            }
        }
    }
}

// ---------------------------------------------------------------------------
// Flash-style attention. Block = (q-tile of 64 rows, head h, batch b).
// 64 threads; each thread owns one q row. Q row + output acc in registers.
// K/V tiles in SMEM (uniform-address broadcast reads). S stored transposed
// Ss[j][r] so per-warp writes/reads are consecutive (conflict-free, no pad).
// ---------------------------------------------------------------------------
__global__ __launch_bounds__(64, 4) void attn_kernel()
{
    __shared__ float Ks[64][64];
    __shared__ float Vs[64][64];
    __shared__ float Ss[64][64];   // [key j][row r]

    const int r  = threadIdx.x;
    const int qt = blockIdx.x;
    const int h  = blockIdx.y;
    const int b  = blockIdx.z;

    const size_t head_base = ((size_t)(b * PH + h)) * PN * PHD;

    // Load Q row (pre-scaled)
    float q[64];
    {
        const float* Qg = g_q + head_base + (size_t)(qt * 64 + r) * PHD;
#pragma unroll
        for (int k = 0; k < 64; k += 4) {
            float4 v = *(const float4*)(Qg + k);
            q[k + 0] = v.x * PSCALE;
            q[k + 1] = v.y * PSCALE;
            q[k + 2] = v.z * PSCALE;
            q[k + 3] = v.w * PSCALE;
        }
    }

    float acc[64];
#pragma unroll
    for (int k = 0; k < 64; k++) acc[k] = 0.f;
    float mrow = -1e30f;
    float lsum = 0.f;

    for (int kt = 0; kt < PN / 64; kt++) {
        __syncthreads();   // previous tile fully consumed
        // Cooperative linear copy of K/V tiles (contiguous 4096 floats each)
        const float4* Kg = (const float4*)(g_k + head_base + (size_t)kt * 64 * PHD);
        const float4* Vg = (const float4*)(g_v + head_base + (size_t)kt * 64 * PHD);
        float4* Ksh = (float4*)&Ks[0][0];
        float4* Vsh = (float4*)&Vs[0][0];
#pragma unroll
        for (int i = 0; i < 16; i++) {
            int idx = r + i * 64;      // 0..1023
            Ksh[idx] = Kg[idx];
            Vsh[idx] = Vg[idx];
        }
        __syncthreads();

        // Pass 1: scores for my row against all 64 keys
        float tmax = -1e30f;
#pragma unroll 4
        for (int j = 0; j < 64; j++) {
            float s = 0.f;
#pragma unroll
            for (int k = 0; k < 64; k += 4) {
                float4 kv = *(const float4*)&Ks[j][k];
                s = fmaf(q[k + 0], kv.x, s);
                s = fmaf(q[k + 1], kv.y, s);
                s = fmaf(q[k + 2], kv.z, s);
                s = fmaf(q[k + 3], kv.w, s);
            }
            Ss[j][r] = s;
            tmax = fmaxf(tmax, s);
        }

        float mnew = fmaxf(mrow, tmax);
        float corr = __expf(mrow - mnew);
        lsum *= corr;
#pragma unroll
        for (int k = 0; k < 64; k++) acc[k] *= corr;

        // Pass 2: softmax weights + PV accumulate
#pragma unroll 2
        for (int j = 0; j < 64; j++) {
            float p = __expf(Ss[j][r] - mnew);
            lsum += p;
#pragma unroll
            for (int k = 0; k < 64; k += 4) {
                float4 vv = *(const float4*)&Vs[j][k];
                acc[k + 0] = fmaf(p, vv.x, acc[k + 0]);
                acc[k + 1] = fmaf(p, vv.y, acc[k + 1]);
                acc[k + 2] = fmaf(p, vv.z, acc[k + 2]);
                acc[k + 3] = fmaf(p, vv.w, acc[k + 3]);
            }
        }
        mrow = mnew;
    }

    // Normalize and write ctx in [B*N, D] layout
    float inv = 1.f / lsum;
    float* Og = g_ctx + ((size_t)(b * PN) + qt * 64 + r) * PD + h * PHD;
#pragma unroll
    for (int k = 0; k < 64; k += 4) {
        float4 o;
        o.x = acc[k + 0] * inv;
        o.y = acc[k + 1] * inv;
        o.z = acc[k + 2] * inv;
        o.w = acc[k + 3] * inv;
        *(float4*)(Og + k) = o;
    }
}

// ---------------------------------------------------------------------------
extern "C" void kernel_launch(void* const* d_in, const int* in_sizes, int n_in,
                              void* d_out, int out_size)
{
    const float* x      = (const float*)d_in[0];
    const float* w_qkv  = (const float*)d_in[1];
    const float* b_qkv  = (const float*)d_in[2];
    const float* w_proj = (const float*)d_in[3];
    const float* b_proj = (const float*)d_in[4];
    float* out = (float*)d_out;

    (void)in_sizes; (void)n_in; (void)out_size;

    // 1) QKV projection: [8192,768] @ [768,2304] -> scattered Q/K/V
    dim3 g1(PQKV / BN, PM / BM);                 // (18, 64)
    gemm_kernel<0><<<g1, 256>>>(x, w_qkv, b_qkv, nullptr, PD, PQKV);

    // 2) Attention per (q-tile, head, batch)
    attn_kernel<<<dim3(PN / 64, PH, PB), 64>>>();

    // 3) Output projection: [8192,768] @ [768,768] + bias -> d_out
    dim3 g3(PD / BN, PM / BM);                   // (6, 64)
    gemm_kernel<1><<<g3, 256>>>(nullptr, w_proj, b_proj, out, PD, PD);
}

// round 4
// speedup vs baseline: 1.4759x; 1.4759x over previous
#include <cuda_runtime.h>
#include <math.h>

// Problem constants
#define PB   8
#define PN   1024
#define PD   768
#define PH   12
#define PHD  64
#define PM   (PB * PN)        // 8192
#define PQKV (3 * PD)         // 2304
#define PSCALE 0.125f         // 64^-0.5

// Scratch (allocation-free rule: __device__ globals)
__device__ float g_q[PB * PH * PN * PHD];     // [B,H,N,64]
__device__ float g_k[PB * PH * PN * PHD];
__device__ float g_v[PB * PH * PN * PHD];
__device__ float g_ctx[(size_t)PM * PD];      // [B*N, D]

// ---------------------------------------------------------------------------
// TF32 warp MMA helper: D += A(16x8) * B(8x8), fp32 accumulate.
// A frag layout: a0=(m=g, k=t), a1=(g+8,t), a2=(g,t+4), a3=(g+8,t+4)
// B frag layout: b0=(k=t, n=g), b1=(k=t+4, n=g)       [g=lane>>2, t=lane&3]
// C/D: c0=(g, 2t), c1=(g, 2t+1), c2=(g+8, 2t), c3=(g+8, 2t+1)
// ---------------------------------------------------------------------------
__device__ __forceinline__ void mma8(float* d, const unsigned* a, const unsigned* b)
{
    asm volatile(
        "mma.sync.aligned.m16n8k8.row.col.f32.tf32.tf32.f32 "
        "{%0,%1,%2,%3}, {%4,%5,%6,%7}, {%8,%9}, {%0,%1,%2,%3};\n"
        : "+f"(d[0]), "+f"(d[1]), "+f"(d[2]), "+f"(d[3])
        : "r"(a[0]), "r"(a[1]), "r"(a[2]), "r"(a[3]), "r"(b[0]), "r"(b[1]));
}

// Error-compensated TF32 split: x = hi + lo, hi = rna-rounded tf32 (exact fp32
// value with low mantissa bits zero), lo = exact residual (|lo| ~ 2^-11 |x|).
__device__ __forceinline__ void split_tf32(float x, unsigned& hi, unsigned& lo)
{
    unsigned h;
    asm("cvt.rna.tf32.f32 %0, %1;\n" : "=r"(h) : "f"(x));
    hi = h;
    lo = __float_as_uint(x - __uint_as_float(h));
}

// ---------------------------------------------------------------------------
// TF32x3 tensor-core GEMM: C[M,NC] = A[M,K] @ W[K,NC] + bias  (~fp32 accurate)
// Tile 128x128x32, 8 warps (2x4), warp tile 64x32.
// MODE 0: A = x, scatter epilogue into g_q/g_k/g_v. MODE 1: A = g_ctx -> C.
// ---------------------------------------------------------------------------
#define GAS 36   // As row stride  (==4 mod 32 -> conflict-free A frags)
#define GBS 136  // Bs row stride  (==8 mod 32 -> conflict-free B frags)

template <int MODE>
__global__ __launch_bounds__(256) void gemm_tc(
    const float* __restrict__ Ain, const float* __restrict__ W,
    const float* __restrict__ bias, float* __restrict__ C,
    int K, int NC)
{
    __shared__ float As[128][GAS];
    __shared__ float Bs[32][GBS];

    const float* A = (MODE == 1) ? (const float*)g_ctx : Ain;

    const int m0 = blockIdx.y * 128;
    const int n0 = blockIdx.x * 128;
    const int t    = threadIdx.x;
    const int lane = t & 31;
    const int w    = t >> 5;
    const int wm   = w >> 2;          // 0..1 (64-row half)
    const int wn   = w & 3;           // 0..3 (32-col quarter)
    const int g    = lane >> 2;       // group id
    const int tq   = lane & 3;        // thread in group

    float acc[4][4][4];
#pragma unroll
    for (int i = 0; i < 4; i++)
#pragma unroll
        for (int j = 0; j < 4; j++)
#pragma unroll
            for (int c = 0; c < 4; c++) acc[i][j][c] = 0.f;

    const int arow = t >> 3;          // 0..31
    const int aseg = (t & 7) * 4;     // k offset (0..28)
    const int brow = t >> 5;          // 0..7
    const int bcol = (t & 31) * 4;

    for (int k0 = 0; k0 < K; k0 += 32) {
        // Fill A tile: 128 rows x 32 k
#pragma unroll
        for (int i = 0; i < 4; i++) {
            int r = arow + i * 32;
            float4 v = *(const float4*)(A + (size_t)(m0 + r) * K + k0 + aseg);
            *(float4*)&As[r][aseg] = v;
        }
        // Fill B tile: 32 k x 128 cols
#pragma unroll
        for (int i = 0; i < 4; i++) {
            int r = brow + i * 8;
            float4 v = *(const float4*)(W + (size_t)(k0 + r) * NC + n0 + bcol);
            *(float4*)&Bs[r][bcol] = v;
        }
        __syncthreads();

#pragma unroll
        for (int ks = 0; ks < 32; ks += 8) {
            unsigned ah[4][4], al[4][4];
#pragma unroll
            for (int mt = 0; mt < 4; mt++) {
                int r = wm * 64 + mt * 16 + g;
                int c = ks + tq;
                split_tf32(As[r][c],         ah[mt][0], al[mt][0]);
                split_tf32(As[r + 8][c],     ah[mt][1], al[mt][1]);
                split_tf32(As[r][c + 4],     ah[mt][2], al[mt][2]);
                split_tf32(As[r + 8][c + 4], ah[mt][3], al[mt][3]);
            }
#pragma unroll
            for (int nt = 0; nt < 4; nt++) {
                int cc = wn * 32 + nt * 8 + g;
                unsigned bh[2], bl[2];
                split_tf32(Bs[ks + tq][cc],     bh[0], bl[0]);
                split_tf32(Bs[ks + 4 + tq][cc], bh[1], bl[1]);
#pragma unroll
                for (int mt = 0; mt < 4; mt++) {
                    mma8(acc[mt][nt], ah[mt], bh);   // hi*hi
                    mma8(acc[mt][nt], al[mt], bh);   // lo*hi
                    mma8(acc[mt][nt], ah[mt], bl);   // hi*lo
                }
            }
        }
        __syncthreads();
    }

    // Epilogue
#pragma unroll
    for (int mt = 0; mt < 4; mt++) {
#pragma unroll
        for (int nt = 0; nt < 4; nt++) {
#pragma unroll
            for (int c = 0; c < 4; c++) {
                int rm = m0 + wm * 64 + mt * 16 + g + ((c >= 2) ? 8 : 0);
                int cn = n0 + wn * 32 + nt * 8 + 2 * tq + (c & 1);
                float v = acc[mt][nt][c] + bias[cn];
                if (MODE == 0) {
                    int which = cn / PD;              // 0=q 1=k 2=v
                    int d  = cn - which * PD;
                    int h  = d >> 6;
                    int hd = d & 63;
                    int bb = rm >> 10;
                    int nn = rm & 1023;
                    float* dst = (which == 0) ? g_q : ((which == 1) ? g_k : g_v);
                    dst[(((size_t)(bb * PH + h)) * PN + nn) * PHD + hd] = v;
                } else {
                    C[(size_t)rm * NC + cn] = v;
                }
            }
        }
    }
}

// ---------------------------------------------------------------------------
// Flash attention with TF32x3 MMA. Block = (64 q-rows, head, batch), 4 warps.
// Warp w owns q rows [w*16, w*16+16). Q hi/lo frags register-resident.
// KPs holds the K tile during S=QK^T, then is overwritten with P (softmax
// weights) for the PV MMA (each warp writes/reads only its own P rows).
// ---------------------------------------------------------------------------
#define KPS 68   // K/P row stride (==4 mod 32)
#define VSS 72   // V row stride   (==8 mod 32)

__global__ __launch_bounds__(128) void attn_tc()
{
    __shared__ float KPs[64][KPS];
    __shared__ float Vs[64][VSS];

    const int t    = threadIdx.x;
    const int lane = t & 31;
    const int w    = t >> 5;
    const int g    = lane >> 2;
    const int tq   = lane & 3;

    const int qt = blockIdx.x;
    const int h  = blockIdx.y;
    const int b  = blockIdx.z;
    const size_t head_base = ((size_t)(b * PH + h)) * PN * PHD;

    // Q fragments (pre-scaled), split hi/lo, register-resident
    unsigned qh[8][4], ql[8][4];
    {
        const float* Qg = g_q + head_base + (size_t)(qt * 64 + w * 16) * PHD;
#pragma unroll
        for (int ks = 0; ks < 8; ks++) {
            int k = ks * 8 + tq;
            split_tf32(Qg[(size_t)g * PHD + k] * PSCALE,           qh[ks][0], ql[ks][0]);
            split_tf32(Qg[(size_t)(g + 8) * PHD + k] * PSCALE,     qh[ks][1], ql[ks][1]);
            split_tf32(Qg[(size_t)g * PHD + k + 4] * PSCALE,       qh[ks][2], ql[ks][2]);
            split_tf32(Qg[(size_t)(g + 8) * PHD + k + 4] * PSCALE, qh[ks][3], ql[ks][3]);
        }
    }

    float o[8][4];
#pragma unroll
    for (int nt = 0; nt < 8; nt++)
#pragma unroll
        for (int c = 0; c < 4; c++) o[nt][c] = 0.f;
    float m0v = -1e30f, m1v = -1e30f;
    float l0 = 0.f, l1 = 0.f;

    for (int kt = 0; kt < PN / 64; kt++) {
        __syncthreads();   // prev tile fully consumed (Vs reads + P reads)
        // Fill K and V tiles (64x64 each)
        {
            const float4* Kg = (const float4*)(g_k + head_base + (size_t)kt * 64 * PHD);
            const float4* Vg = (const float4*)(g_v + head_base + (size_t)kt * 64 * PHD);
#pragma unroll
            for (int i = 0; i < 8; i++) {
                int idx = t + i * 128;        // 0..1023 float4s
                int row = idx >> 4;
                int seg = (idx & 15) * 4;
                *(float4*)&KPs[row][seg] = Kg[idx];
                *(float4*)&Vs[row][seg]  = Vg[idx];
            }
        }
        __syncthreads();

        // S = Q @ K^T for my 16 rows x 64 keys (3-MMA compensated)
        float s[8][4];
#pragma unroll
        for (int nt = 0; nt < 8; nt++)
#pragma unroll
            for (int c = 0; c < 4; c++) s[nt][c] = 0.f;

#pragma unroll
        for (int nt = 0; nt < 8; nt++) {
            int key = nt * 8 + g;
#pragma unroll
            for (int ks = 0; ks < 8; ks++) {
                unsigned bh[2], bl[2];
                split_tf32(KPs[key][ks * 8 + tq],     bh[0], bl[0]);
                split_tf32(KPs[key][ks * 8 + 4 + tq], bh[1], bl[1]);
                mma8(s[nt], qh[ks], bh);
                mma8(s[nt], ql[ks], bh);
                mma8(s[nt], qh[ks], bl);
            }
        }

        // Online softmax (rows r0 = w*16+g, r1 = r0+8)
        float tmax0 = -1e30f, tmax1 = -1e30f;
#pragma unroll
        for (int nt = 0; nt < 8; nt++) {
            tmax0 = fmaxf(tmax0, fmaxf(s[nt][0], s[nt][1]));
            tmax1 = fmaxf(tmax1, fmaxf(s[nt][2], s[nt][3]));
        }
        tmax0 = fmaxf(tmax0, __shfl_xor_sync(0xffffffffu, tmax0, 1));
        tmax0 = fmaxf(tmax0, __shfl_xor_sync(0xffffffffu, tmax0, 2));
        tmax1 = fmaxf(tmax1, __shfl_xor_sync(0xffffffffu, tmax1, 1));
        tmax1 = fmaxf(tmax1, __shfl_xor_sync(0xffffffffu, tmax1, 2));

        float mnew0 = fmaxf(m0v, tmax0);
        float mnew1 = fmaxf(m1v, tmax1);
        float corr0 = __expf(m0v - mnew0);
        float corr1 = __expf(m1v - mnew1);
#pragma unroll
        for (int nt = 0; nt < 8; nt++) {
            o[nt][0] *= corr0; o[nt][1] *= corr0;
            o[nt][2] *= corr1; o[nt][3] *= corr1;
        }

        __syncthreads();   // everyone done reading K before P overwrites it

        float rs0 = 0.f, rs1 = 0.f;
        const int prow = w * 16 + g;
#pragma unroll
        for (int nt = 0; nt < 8; nt++) {
            float p0 = __expf(s[nt][0] - mnew0);
            float p1 = __expf(s[nt][1] - mnew0);
            float p2 = __expf(s[nt][2] - mnew1);
            float p3 = __expf(s[nt][3] - mnew1);
            rs0 += p0 + p1;
            rs1 += p2 + p3;
            int col = nt * 8 + 2 * tq;
            float2 lo; lo.x = p0; lo.y = p1;
            float2 hi; hi.x = p2; hi.y = p3;
            *(float2*)&KPs[prow][col]     = lo;
            *(float2*)&KPs[prow + 8][col] = hi;
        }
        rs0 += __shfl_xor_sync(0xffffffffu, rs0, 1);
        rs0 += __shfl_xor_sync(0xffffffffu, rs0, 2);
        rs1 += __shfl_xor_sync(0xffffffffu, rs1, 1);
        rs1 += __shfl_xor_sync(0xffffffffu, rs1, 2);
        l0 = l0 * corr0 + rs0;
        l1 = l1 * corr1 + rs1;
        m0v = mnew0;
        m1v = mnew1;
        __syncwarp();      // P rows visible to own warp

        // O += P @ V (3-MMA compensated; A = my P rows, B = V tile)
#pragma unroll
        for (int ks = 0; ks < 8; ks++) {
            int kk = ks * 8 + tq;
            unsigned ah[4], al[4];
            split_tf32(KPs[prow][kk],         ah[0], al[0]);
            split_tf32(KPs[prow + 8][kk],     ah[1], al[1]);
            split_tf32(KPs[prow][kk + 4],     ah[2], al[2]);
            split_tf32(KPs[prow + 8][kk + 4], ah[3], al[3]);
#pragma unroll
            for (int nt = 0; nt < 8; nt++) {
                unsigned bh[2], bl[2];
                split_tf32(Vs[ks * 8 + tq][nt * 8 + g],     bh[0], bl[0]);
                split_tf32(Vs[ks * 8 + 4 + tq][nt * 8 + g], bh[1], bl[1]);
                mma8(o[nt], ah, bh);
                mma8(o[nt], al, bh);
                mma8(o[nt], ah, bl);
            }
        }
    }

    // Normalize and write ctx in [B*N, D] layout
    float inv0 = 1.f / l0;
    float inv1 = 1.f / l1;
    float* Og0 = g_ctx + ((size_t)(b * PN) + qt * 64 + w * 16 + g) * PD + h * PHD;
    float* Og1 = Og0 + (size_t)8 * PD;
#pragma unroll
    for (int nt = 0; nt < 8; nt++) {
        int col = nt * 8 + 2 * tq;
        float2 lo; lo.x = o[nt][0] * inv0; lo.y = o[nt][1] * inv0;
        float2 hi; hi.x = o[nt][2] * inv1; hi.y = o[nt][3] * inv1;
        *(float2*)(Og0 + col) = lo;
        *(float2*)(Og1 + col) = hi;
    }
}

// ---------------------------------------------------------------------------
extern "C" void kernel_launch(void* const* d_in, const int* in_sizes, int n_in,
                              void* d_out, int out_size)
{
    const float* x      = (const float*)d_in[0];
    const float* w_qkv  = (const float*)d_in[1];
    const float* b_qkv  = (const float*)d_in[2];
    const float* w_proj = (const float*)d_in[3];
    const float* b_proj = (const float*)d_in[4];
    float* out = (float*)d_out;

    (void)in_sizes; (void)n_in; (void)out_size;

    // 1) QKV projection: [8192,768] @ [768,2304] -> scattered Q/K/V
    dim3 g1(PQKV / 128, PM / 128);               // (18, 64)
    gemm_tc<0><<<g1, 256>>>(x, w_qkv, b_qkv, nullptr, PD, PQKV);

    // 2) Attention per (q-tile, head, batch)
    attn_tc<<<dim3(PN / 64, PH, PB), 128>>>();

    // 3) Output projection: [8192,768] @ [768,768] + bias -> d_out
    dim3 g3(PD / 128, PM / 128);                 // (6, 64)
    gemm_tc<1><<<g3, 256>>>(nullptr, w_proj, b_proj, out, PD, PD);
}

// round 6
// speedup vs baseline: 2.3577x; 1.5974x over previous
#include <cuda_runtime.h>
#include <math.h>

// Problem constants
#define PB   8
#define PN   1024
#define PD   768
#define PH   12
#define PHD  64
#define PM   (PB * PN)        // 8192
#define PQKV (3 * PD)         // 2304
#define PSCALE 0.125f         // 64^-0.5

// Scratch (allocation-free rule: __device__ globals)
__device__ float g_q[PB * PH * PN * PHD];     // [B,H,N,64]
__device__ float g_k[PB * PH * PN * PHD];
__device__ float g_v[PB * PH * PN * PHD];
__device__ float g_ctx[(size_t)PM * PD];      // [B*N, D]

// ---------------------------------------------------------------------------
// bf16 warp MMA: D += A(16x16) * B(16x8), fp32 accumulate. m16n8k16.
// A frag (row-major, pairs along k packed in 32b): a0=(g,2t:2t+1) a1=(g+8,..)
// a2=(g,2t+8:2t+9) a3=(g+8,..)     [g=lane>>2, t=lane&3]
// B frag (col-major): b0=(k=2t:2t+1, n=g), b1=(k=2t+8:2t+9, n=g)
// C/D: c0=(g,2t) c1=(g,2t+1) c2=(g+8,2t) c3=(g+8,2t+1)
// ---------------------------------------------------------------------------
__device__ __forceinline__ void mma16(float* d, const unsigned* a, const unsigned* b)
{
    asm volatile(
        "mma.sync.aligned.m16n8k16.row.col.f32.bf16.bf16.f32 "
        "{%0,%1,%2,%3}, {%4,%5,%6,%7}, {%8,%9}, {%0,%1,%2,%3};\n"
        : "+f"(d[0]), "+f"(d[1]), "+f"(d[2]), "+f"(d[3])
        : "r"(a[0]), "r"(a[1]), "r"(a[2]), "r"(a[3]), "r"(b[0]), "r"(b[1]));
}

// Split (x0,x1) into packed bf16x2 hi word + bf16x2 lo (residual) word.
// Lower 16 bits hold x0 (even k), upper hold x1 (odd k).
__device__ __forceinline__ void split2(float x0, float x1, unsigned& h, unsigned& l)
{
    unsigned hh;
    asm("cvt.rn.bf16x2.f32 %0, %1, %2;" : "=r"(hh) : "f"(x1), "f"(x0));
    float h0 = __uint_as_float(hh << 16);
    float h1 = __uint_as_float(hh & 0xffff0000u);
    unsigned ll;
    asm("cvt.rn.bf16x2.f32 %0, %1, %2;" : "=r"(ll) : "f"(x1 - h1), "f"(x0 - h0));
    h = hh; l = ll;
}

// ---------------------------------------------------------------------------
// bf16x3 tensor-core GEMM: C[M,NC] = A[M,K] @ W[K,NC] + bias (~fp32 accurate)
// Tile 128x128x32, 8 warps (2x4), warp tile 64x32. hi/lo split at tile load.
// SMEM word layout: Ah/Al[row][kp] = A[row][2kp:2kp+1] packed (stride 20:
// banks 20g+tq all distinct). Bh/Bl[kp][n] = W[2kp:2kp+1][n] packed
// (stride 136 == 8 mod 32: banks 8tq+g all distinct).
// MODE 0: A = x, scatter epilogue into g_q/g_k/g_v. MODE 1: A = g_ctx -> C.
// ---------------------------------------------------------------------------
#define SAW 20
#define SBW 136

template <int MODE>
__global__ __launch_bounds__(256) void gemm_tc(
    const float* __restrict__ Ain, const float* __restrict__ W,
    const float* __restrict__ bias, float* __restrict__ C,
    int K, int NC)
{
    __shared__ unsigned Ah[128][SAW], Al[128][SAW];
    __shared__ unsigned Bh[16][SBW],  Bl[16][SBW];

    const float* A = (MODE == 1) ? (const float*)g_ctx : Ain;

    const int m0 = blockIdx.y * 128;
    const int n0 = blockIdx.x * 128;
    const int t    = threadIdx.x;
    const int lane = t & 31;
    const int w    = t >> 5;
    const int wm   = w >> 2;          // 0..1
    const int wn   = w & 3;           // 0..3
    const int g    = lane >> 2;
    const int tq   = lane & 3;

    float acc[4][4][4];
#pragma unroll
    for (int i = 0; i < 4; i++)
#pragma unroll
        for (int j = 0; j < 4; j++)
#pragma unroll
            for (int c = 0; c < 4; c++) acc[i][j][c] = 0.f;

    const int arow = t >> 3;          // 0..31
    const int akp  = (t & 7) * 2;     // pair index 0..14
    const int bkp  = t >> 5;          // 0..7
    const int bn   = t & 31;

    for (int k0 = 0; k0 < K; k0 += 32) {
        // A tile: 128 rows x 32 k -> hi/lo packed pairs
#pragma unroll
        for (int i = 0; i < 4; i++) {
            int r = arow + i * 32;
            float4 v = *(const float4*)(A + (size_t)(m0 + r) * K + k0 + akp * 2);
            unsigned h0, l0, h1, l1;
            split2(v.x, v.y, h0, l0);
            split2(v.z, v.w, h1, l1);
            uint2 ph; ph.x = h0; ph.y = h1;
            uint2 pl; pl.x = l0; pl.y = l1;
            *(uint2*)&Ah[r][akp] = ph;
            *(uint2*)&Al[r][akp] = pl;
        }
        // B tile: 32 k x 128 n -> pairs along k
#pragma unroll
        for (int i = 0; i < 2; i++) {
            int kp = bkp + i * 8;
#pragma unroll
            for (int j = 0; j < 4; j++) {
                int n = bn + j * 32;
                float f0 = W[(size_t)(k0 + 2 * kp)     * NC + n0 + n];
                float f1 = W[(size_t)(k0 + 2 * kp + 1) * NC + n0 + n];
                unsigned h, l;
                split2(f0, f1, h, l);
                Bh[kp][n] = h;
                Bl[kp][n] = l;
            }
        }
        __syncthreads();

#pragma unroll
        for (int ks = 0; ks < 2; ks++) {
            unsigned ah[4][4], al[4][4];
#pragma unroll
            for (int mt = 0; mt < 4; mt++) {
                int r  = wm * 64 + mt * 16 + g;
                int kq = ks * 8 + tq;
                ah[mt][0] = Ah[r][kq];     al[mt][0] = Al[r][kq];
                ah[mt][1] = Ah[r + 8][kq]; al[mt][1] = Al[r + 8][kq];
                ah[mt][2] = Ah[r][kq + 4];     al[mt][2] = Al[r][kq + 4];
                ah[mt][3] = Ah[r + 8][kq + 4]; al[mt][3] = Al[r + 8][kq + 4];
            }
#pragma unroll
            for (int nt = 0; nt < 4; nt++) {
                int cc = wn * 32 + nt * 8 + g;
                unsigned bh[2], bl[2];
                bh[0] = Bh[ks * 8 + tq][cc];     bl[0] = Bl[ks * 8 + tq][cc];
                bh[1] = Bh[ks * 8 + tq + 4][cc]; bl[1] = Bl[ks * 8 + tq + 4][cc];
#pragma unroll
                for (int mt = 0; mt < 4; mt++) {
                    mma16(acc[mt][nt], ah[mt], bh);   // hi*hi
                    mma16(acc[mt][nt], al[mt], bh);   // lo*hi
                    mma16(acc[mt][nt], ah[mt], bl);   // hi*lo
                }
            }
        }
        __syncthreads();
    }

    // Epilogue (C frag: c0=(g,2tq) c1=(g,2tq+1) c2=(g+8,2tq) c3=(g+8,2tq+1))
#pragma unroll
    for (int mt = 0; mt < 4; mt++) {
#pragma unroll
        for (int nt = 0; nt < 4; nt++) {
#pragma unroll
            for (int c = 0; c < 4; c++) {
                int rm = m0 + wm * 64 + mt * 16 + g + ((c >= 2) ? 8 : 0);
                int cn = n0 + wn * 32 + nt * 8 + 2 * tq + (c & 1);
                float v = acc[mt][nt][c] + bias[cn];
                if (MODE == 0) {
                    int which = cn / PD;              // 0=q 1=k 2=v
                    int d  = cn - which * PD;
                    int h  = d >> 6;
                    int hd = d & 63;
                    int bb = rm >> 10;
                    int nn = rm & 1023;
                    float* dst = (which == 0) ? g_q : ((which == 1) ? g_k : g_v);
                    dst[(((size_t)(bb * PH + h)) * PN + nn) * PHD + hd] = v;
                } else {
                    C[(size_t)rm * NC + cn] = v;
                }
            }
        }
    }
}

// ---------------------------------------------------------------------------
// Flash attention, bf16x3 m16n8k16. Block = (64 q-rows, head, batch), 4 warps.
// Warp w owns q rows [w*16, w*16+16). Q hi/lo frags register-resident.
// Kh/Kl[key][dp]: K pairs along d (B operand of S).   stride 36 (4g+tq free)
// Vh/Vl[d][kp]:  V pairs along key (B operand of PV). stride 36
// P fragments for PV come straight from softmax registers (no SMEM staging).
// ---------------------------------------------------------------------------
#define SKW 36

__global__ __launch_bounds__(128) void attn_tc()
{
    __shared__ unsigned Kh[64][SKW], Kl[64][SKW];
    __shared__ unsigned Vh[64][SKW], Vl[64][SKW];

    const int t    = threadIdx.x;
    const int lane = t & 31;
    const int w    = t >> 5;
    const int g    = lane >> 2;
    const int tq   = lane & 3;

    const int qt = blockIdx.x;
    const int h  = blockIdx.y;
    const int b  = blockIdx.z;
    const size_t head_base = ((size_t)(b * PH + h)) * PN * PHD;

    // Q fragments (pre-scaled), hi/lo, register-resident. 4 k16-steps.
    unsigned qh[4][4], ql[4][4];
    {
        const float* Qg = g_q + head_base + (size_t)(qt * 64 + w * 16) * PHD;
#pragma unroll
        for (int ks = 0; ks < 4; ks++) {
            int d = ks * 16 + 2 * tq;
            float2 v0 = *(const float2*)(Qg + (size_t)g * PHD + d);
            float2 v1 = *(const float2*)(Qg + (size_t)(g + 8) * PHD + d);
            float2 v2 = *(const float2*)(Qg + (size_t)g * PHD + d + 8);
            float2 v3 = *(const float2*)(Qg + (size_t)(g + 8) * PHD + d + 8);
            split2(v0.x * PSCALE, v0.y * PSCALE, qh[ks][0], ql[ks][0]);
            split2(v1.x * PSCALE, v1.y * PSCALE, qh[ks][1], ql[ks][1]);
            split2(v2.x * PSCALE, v2.y * PSCALE, qh[ks][2], ql[ks][2]);
            split2(v3.x * PSCALE, v3.y * PSCALE, qh[ks][3], ql[ks][3]);
        }
    }

    float o[8][4];
#pragma unroll
    for (int nt = 0; nt < 8; nt++)
#pragma unroll
        for (int c = 0; c < 4; c++) o[nt][c] = 0.f;
    float m0v = -1e30f, m1v = -1e30f;
    float l0 = 0.f, l1 = 0.f;

    // V-fill lane decomposition: kq = lane&3, dq = lane>>2
    const int vkq = lane & 3;
    const int vdq = lane >> 2;

    for (int kt = 0; kt < PN / 64; kt++) {
        __syncthreads();   // prev tile fully consumed
        // K tile: 64 keys x 64 d, packed pairs along d
        {
            const float4* Kg = (const float4*)(g_k + head_base + (size_t)kt * 64 * PHD);
#pragma unroll
            for (int i = 0; i < 8; i++) {
                int idx = t + i * 128;          // 0..1023
                int row = idx >> 4;
                int dp0 = (idx & 15) * 2;
                float4 v = Kg[idx];
                unsigned h0, lo0, h1, lo1;
                split2(v.x, v.y, h0, lo0);
                split2(v.z, v.w, h1, lo1);
                uint2 ph; ph.x = h0; ph.y = h1;
                uint2 pl; pl.x = lo0; pl.y = lo1;
                *(uint2*)&Kh[row][dp0] = ph;
                *(uint2*)&Kl[row][dp0] = pl;
            }
        }
        // V tile transposed-packed: Vh[d][kp] = (V[2kp][d], V[2kp+1][d])
        {
            const float* Vg = g_v + head_base + (size_t)kt * 64 * PHD;
#pragma unroll
            for (int i = 0; i < 8; i++) {
                int kp = vkq + 4 * i;
                int d0 = 2 * vdq + 16 * w;
                float2 f0 = *(const float2*)(Vg + (size_t)(2 * kp) * PHD + d0);
                float2 f1 = *(const float2*)(Vg + (size_t)(2 * kp + 1) * PHD + d0);
                unsigned hA, lA, hB, lB;
                split2(f0.x, f1.x, hA, lA);
                split2(f0.y, f1.y, hB, lB);
                Vh[d0][kp] = hA;     Vl[d0][kp] = lA;
                Vh[d0 + 1][kp] = hB; Vl[d0 + 1][kp] = lB;
            }
        }
        __syncthreads();

        // S = Q @ K^T (3-MMA compensated), 16 rows x 64 keys
        float s[8][4];
#pragma unroll
        for (int nt = 0; nt < 8; nt++)
#pragma unroll
            for (int c = 0; c < 4; c++) s[nt][c] = 0.f;

#pragma unroll
        for (int nt = 0; nt < 8; nt++) {
            int key = nt * 8 + g;
#pragma unroll
            for (int ks = 0; ks < 4; ks++) {
                unsigned bh[2], bl[2];
                bh[0] = Kh[key][ks * 8 + tq];     bl[0] = Kl[key][ks * 8 + tq];
                bh[1] = Kh[key][ks * 8 + tq + 4]; bl[1] = Kl[key][ks * 8 + tq + 4];
                mma16(s[nt], qh[ks], bh);
                mma16(s[nt], ql[ks], bh);
                mma16(s[nt], qh[ks], bl);
            }
        }

        // Online softmax (rows r0 = w*16+g, r1 = r0+8)
        float tmax0 = -1e30f, tmax1 = -1e30f;
#pragma unroll
        for (int nt = 0; nt < 8; nt++) {
            tmax0 = fmaxf(tmax0, fmaxf(s[nt][0], s[nt][1]));
            tmax1 = fmaxf(tmax1, fmaxf(s[nt][2], s[nt][3]));
        }
        tmax0 = fmaxf(tmax0, __shfl_xor_sync(0xffffffffu, tmax0, 1));
        tmax0 = fmaxf(tmax0, __shfl_xor_sync(0xffffffffu, tmax0, 2));
        tmax1 = fmaxf(tmax1, __shfl_xor_sync(0xffffffffu, tmax1, 1));
        tmax1 = fmaxf(tmax1, __shfl_xor_sync(0xffffffffu, tmax1, 2));

        float mnew0 = fmaxf(m0v, tmax0);
        float mnew1 = fmaxf(m1v, tmax1);
        float corr0 = __expf(m0v - mnew0);
        float corr1 = __expf(m1v - mnew1);
#pragma unroll
        for (int nt = 0; nt < 8; nt++) {
            o[nt][0] *= corr0; o[nt][1] *= corr0;
            o[nt][2] *= corr1; o[nt][3] *= corr1;
        }

        float rs0 = 0.f, rs1 = 0.f;
#pragma unroll
        for (int nt = 0; nt < 8; nt++) {
            s[nt][0] = __expf(s[nt][0] - mnew0);
            s[nt][1] = __expf(s[nt][1] - mnew0);
            s[nt][2] = __expf(s[nt][2] - mnew1);
            s[nt][3] = __expf(s[nt][3] - mnew1);
            rs0 += s[nt][0] + s[nt][1];
            rs1 += s[nt][2] + s[nt][3];
        }
        rs0 += __shfl_xor_sync(0xffffffffu, rs0, 1);
        rs0 += __shfl_xor_sync(0xffffffffu, rs0, 2);
        rs1 += __shfl_xor_sync(0xffffffffu, rs1, 1);
        rs1 += __shfl_xor_sync(0xffffffffu, rs1, 2);
        l0 = l0 * corr0 + rs0;
        l1 = l1 * corr1 + rs1;
        m0v = mnew0;
        m1v = mnew1;

        // O += P @ V. P frags come straight from s registers:
        // A frag for k16-block ks: a0=(g, keys 16ks+2tq:+1)=s[2ks][0:1],
        // a1=s[2ks][2:3] (row g+8), a2=s[2ks+1][0:1], a3=s[2ks+1][2:3].
#pragma unroll
        for (int ks = 0; ks < 4; ks++) {
            unsigned ah[4], al[4];
            split2(s[2 * ks][0],     s[2 * ks][1],     ah[0], al[0]);
            split2(s[2 * ks][2],     s[2 * ks][3],     ah[1], al[1]);
            split2(s[2 * ks + 1][0], s[2 * ks + 1][1], ah[2], al[2]);
            split2(s[2 * ks + 1][2], s[2 * ks + 1][3], ah[3], al[3]);
#pragma unroll
            for (int nt = 0; nt < 8; nt++) {
                int dcol = nt * 8 + g;
                unsigned bh[2], bl[2];
                bh[0] = Vh[dcol][ks * 8 + tq];     bl[0] = Vl[dcol][ks * 8 + tq];
                bh[1] = Vh[dcol][ks * 8 + tq + 4]; bl[1] = Vl[dcol][ks * 8 + tq + 4];
                mma16(o[nt], ah, bh);
                mma16(o[nt], al, bh);
                mma16(o[nt], ah, bl);
            }
        }
    }

    // Normalize and write ctx in [B*N, D] layout
    float inv0 = 1.f / l0;
    float inv1 = 1.f / l1;
    float* Og0 = g_ctx + ((size_t)(b * PN) + qt * 64 + w * 16 + g) * PD + h * PHD;
    float* Og1 = Og0 + (size_t)8 * PD;
#pragma unroll
    for (int nt = 0; nt < 8; nt++) {
        int col = nt * 8 + 2 * tq;
        float2 lo; lo.x = o[nt][0] * inv0; lo.y = o[nt][1] * inv0;
        float2 hi; hi.x = o[nt][2] * inv1; hi.y = o[nt][3] * inv1;
        *(float2*)(Og0 + col) = lo;
        *(float2*)(Og1 + col) = hi;
    }
}

// ---------------------------------------------------------------------------
extern "C" void kernel_launch(void* const* d_in, const int* in_sizes, int n_in,
                              void* d_out, int out_size)
{
    const float* x      = (const float*)d_in[0];
    const float* w_qkv  = (const float*)d_in[1];
    const float* b_qkv  = (const float*)d_in[2];
    const float* w_proj = (const float*)d_in[3];
    const float* b_proj = (const float*)d_in[4];
    float* out = (float*)d_out;

    (void)in_sizes; (void)n_in; (void)out_size;

    // 1) QKV projection: [8192,768] @ [768,2304] -> scattered Q/K/V
    dim3 g1(PQKV / 128, PM / 128);               // (18, 64)
    gemm_tc<0><<<g1, 256>>>(x, w_qkv, b_qkv, nullptr, PD, PQKV);

    // 2) Attention per (q-tile, head, batch)
    attn_tc<<<dim3(PN / 64, PH, PB), 128>>>();

    // 3) Output projection: [8192,768] @ [768,768] + bias -> d_out
    dim3 g3(PD / 128, PM / 128);                 // (6, 64)
    gemm_tc<1><<<g3, 256>>>(nullptr, w_proj, b_proj, out, PD, PD);
}

// round 7
// speedup vs baseline: 2.6849x; 1.1388x over previous
#include <cuda_runtime.h>
#include <math.h>

// Problem constants
#define PB   8
#define PN   1024
#define PD   768
#define PH   12
#define PHD  64
#define PM   (PB * PN)        // 8192
#define PQKV (3 * PD)         // 2304
#define PSCALE 0.125f         // 64^-0.5

// Scratch (allocation-free rule: __device__ globals)
__device__ float g_q[PB * PH * PN * PHD];     // [B,H,N,64]
__device__ float g_k[PB * PH * PN * PHD];
__device__ float g_v[PB * PH * PN * PHD];
__device__ float g_ctx[(size_t)PM * PD];      // [B*N, D]

// ---------------------------------------------------------------------------
// bf16 warp MMA: D += A(16x16) * B(16x8), fp32 accumulate. m16n8k16.
// A frag (row-major, k-pairs packed): a0=(g,2t:2t+1) a1=(g+8,..) a2=(g,2t+8:2t+9)
// a3=(g+8,..)   B frag (col-major): b0=(k=2t:2t+1,n=g) b1=(k=2t+8:2t+9,n=g)
// C/D: c0=(g,2t) c1=(g,2t+1) c2=(g+8,2t) c3=(g+8,2t+1)   [g=lane>>2, t=lane&3]
// ---------------------------------------------------------------------------
__device__ __forceinline__ void mma16(float* d, const unsigned* a, const unsigned* b)
{
    asm volatile(
        "mma.sync.aligned.m16n8k16.row.col.f32.bf16.bf16.f32 "
        "{%0,%1,%2,%3}, {%4,%5,%6,%7}, {%8,%9}, {%0,%1,%2,%3};\n"
        : "+f"(d[0]), "+f"(d[1]), "+f"(d[2]), "+f"(d[3])
        : "r"(a[0]), "r"(a[1]), "r"(a[2]), "r"(a[3]), "r"(b[0]), "r"(b[1]));
}

// Split (x0,x1) into packed bf16x2 hi word + bf16x2 lo (residual) word.
__device__ __forceinline__ void split2(float x0, float x1, unsigned& h, unsigned& l)
{
    unsigned hh;
    asm("cvt.rn.bf16x2.f32 %0, %1, %2;" : "=r"(hh) : "f"(x1), "f"(x0));
    float h0 = __uint_as_float(hh << 16);
    float h1 = __uint_as_float(hh & 0xffff0000u);
    unsigned ll;
    asm("cvt.rn.bf16x2.f32 %0, %1, %2;" : "=r"(ll) : "f"(x1 - h1), "f"(x0 - h0));
    h = hh; l = ll;
}

// ---------------------------------------------------------------------------
// bf16x3 GEMM, double-buffered + register-prefetched.
// C[M,NC] = A[M,K] @ W[K,NC] + bias. Tile 128x128x32, 8 warps, 64x32/warp.
// Dynamic SMEM: 2 buffers x { Ah[128][20], Al, Bh[16][136], Bl }.
// MODE 0: A = x, scatter epilogue into g_q/g_k/g_v. MODE 1: A = g_ctx -> C.
// ---------------------------------------------------------------------------
#define SAW 20
#define SBW 136
#define ABUF_WORDS (128 * SAW)
#define BBUF_WORDS (16 * SBW)
#define BUF_WORDS  (2 * ABUF_WORDS + 2 * BBUF_WORDS)
#define GEMM_SMEM_BYTES (2 * BUF_WORDS * 4)

template <int MODE>
__global__ __launch_bounds__(256) void gemm_tc(
    const float* __restrict__ Ain, const float* __restrict__ W,
    const float* __restrict__ bias, float* __restrict__ C,
    int K, int NC)
{
    extern __shared__ unsigned dsm[];

    const float* A = (MODE == 1) ? (const float*)g_ctx : Ain;

    const int m0 = blockIdx.y * 128;
    const int n0 = blockIdx.x * 128;
    const int t    = threadIdx.x;
    const int lane = t & 31;
    const int w    = t >> 5;
    const int wm   = w >> 2;          // 0..1
    const int wn   = w & 3;           // 0..3
    const int g    = lane >> 2;
    const int tq   = lane & 3;

    float acc[4][4][4];
#pragma unroll
    for (int i = 0; i < 4; i++)
#pragma unroll
        for (int j = 0; j < 4; j++)
#pragma unroll
            for (int c = 0; c < 4; c++) acc[i][j][c] = 0.f;

    const int arow = t >> 3;          // 0..31
    const int akp  = (t & 7) * 2;     // pair index 0..14
    const int bkp  = t >> 5;          // 0..7
    const int bn   = t & 31;

    const int NT = K / 32;

    float4 aR[4];                     // prefetch registers
    float2 bR[2][4];

    auto ldg_tile = [&](int kt) {
        int k0 = kt * 32;
#pragma unroll
        for (int i = 0; i < 4; i++) {
            int r = arow + i * 32;
            aR[i] = *(const float4*)(A + (size_t)(m0 + r) * K + k0 + akp * 2);
        }
#pragma unroll
        for (int i = 0; i < 2; i++) {
            int kp = bkp + i * 8;
#pragma unroll
            for (int j = 0; j < 4; j++) {
                int n = bn + j * 32;
                bR[i][j].x = W[(size_t)(k0 + 2 * kp)     * NC + n0 + n];
                bR[i][j].y = W[(size_t)(k0 + 2 * kp + 1) * NC + n0 + n];
            }
        }
    };

    auto store_tile = [&](int bi) {
        unsigned* AhP = dsm + bi * BUF_WORDS;
        unsigned* AlP = AhP + ABUF_WORDS;
        unsigned* BhP = AlP + ABUF_WORDS;
        unsigned* BlP = BhP + BBUF_WORDS;
#pragma unroll
        for (int i = 0; i < 4; i++) {
            int r = arow + i * 32;
            unsigned h0, l0, h1, l1;
            split2(aR[i].x, aR[i].y, h0, l0);
            split2(aR[i].z, aR[i].w, h1, l1);
            uint2 ph; ph.x = h0; ph.y = h1;
            uint2 pl; pl.x = l0; pl.y = l1;
            *(uint2*)&AhP[r * SAW + akp] = ph;
            *(uint2*)&AlP[r * SAW + akp] = pl;
        }
#pragma unroll
        for (int i = 0; i < 2; i++) {
            int kp = bkp + i * 8;
#pragma unroll
            for (int j = 0; j < 4; j++) {
                int n = bn + j * 32;
                unsigned h, l;
                split2(bR[i][j].x, bR[i][j].y, h, l);
                BhP[kp * SBW + n] = h;
                BlP[kp * SBW + n] = l;
            }
        }
    };

    // Prologue: fill buffer 0
    ldg_tile(0);
    store_tile(0);
    __syncthreads();

    for (int kt = 0; kt < NT; kt++) {
        if (kt + 1 < NT) ldg_tile(kt + 1);   // issue LDGs early (hidden by MMAs)

        const unsigned* AhP = dsm + (kt & 1) * BUF_WORDS;
        const unsigned* AlP = AhP + ABUF_WORDS;
        const unsigned* BhP = AlP + ABUF_WORDS;
        const unsigned* BlP = BhP + BBUF_WORDS;

#pragma unroll
        for (int ks = 0; ks < 2; ks++) {
            unsigned ah[4][4], al[4][4];
#pragma unroll
            for (int mt = 0; mt < 4; mt++) {
                int r  = wm * 64 + mt * 16 + g;
                int kq = ks * 8 + tq;
                ah[mt][0] = AhP[r * SAW + kq];           al[mt][0] = AlP[r * SAW + kq];
                ah[mt][1] = AhP[(r + 8) * SAW + kq];     al[mt][1] = AlP[(r + 8) * SAW + kq];
                ah[mt][2] = AhP[r * SAW + kq + 4];       al[mt][2] = AlP[r * SAW + kq + 4];
                ah[mt][3] = AhP[(r + 8) * SAW + kq + 4]; al[mt][3] = AlP[(r + 8) * SAW + kq + 4];
            }
#pragma unroll
            for (int nt = 0; nt < 4; nt++) {
                int cc = wn * 32 + nt * 8 + g;
                unsigned bh[2], bl[2];
                bh[0] = BhP[(ks * 8 + tq) * SBW + cc];     bl[0] = BlP[(ks * 8 + tq) * SBW + cc];
                bh[1] = BhP[(ks * 8 + tq + 4) * SBW + cc]; bl[1] = BlP[(ks * 8 + tq + 4) * SBW + cc];
#pragma unroll
                for (int mt = 0; mt < 4; mt++) {
                    mma16(acc[mt][nt], ah[mt], bh);   // hi*hi
                    mma16(acc[mt][nt], al[mt], bh);   // lo*hi
                    mma16(acc[mt][nt], ah[mt], bl);   // hi*lo
                }
            }
        }

        if (kt + 1 < NT) store_tile((kt + 1) & 1);
        __syncthreads();
    }

    // Epilogue
#pragma unroll
    for (int mt = 0; mt < 4; mt++) {
#pragma unroll
        for (int nt = 0; nt < 4; nt++) {
#pragma unroll
            for (int c = 0; c < 4; c++) {
                int rm = m0 + wm * 64 + mt * 16 + g + ((c >= 2) ? 8 : 0);
                int cn = n0 + wn * 32 + nt * 8 + 2 * tq + (c & 1);
                float v = acc[mt][nt][c] + bias[cn];
                if (MODE == 0) {
                    int which = cn / PD;              // 0=q 1=k 2=v
                    int d  = cn - which * PD;
                    int h  = d >> 6;
                    int hd = d & 63;
                    int bb = rm >> 10;
                    int nn = rm & 1023;
                    float* dst = (which == 0) ? g_q : ((which == 1) ? g_k : g_v);
                    dst[(((size_t)(bb * PH + h)) * PN + nn) * PHD + hd] = v;
                } else {
                    C[(size_t)rm * NC + cn] = v;
                }
            }
        }
    }
}

// ---------------------------------------------------------------------------
// Flash attention, bf16x3 m16n8k16, register-prefetched K/V tiles.
// Block = (64 q-rows, head, batch), 4 warps; warp w owns rows [16w,16w+16).
// Kh/Kl[key][dp]: K pairs along d.  Vh/Vl[d][kp]: V pairs along key.
// P fragments come straight from softmax registers.
// ---------------------------------------------------------------------------
#define SKW 36

__global__ __launch_bounds__(128) void attn_tc()
{
    __shared__ unsigned Kh[64][SKW], Kl[64][SKW];
    __shared__ unsigned Vh[64][SKW], Vl[64][SKW];

    const int t    = threadIdx.x;
    const int lane = t & 31;
    const int w    = t >> 5;
    const int g    = lane >> 2;
    const int tq   = lane & 3;

    const int qt = blockIdx.x;
    const int h  = blockIdx.y;
    const int b  = blockIdx.z;
    const size_t head_base = ((size_t)(b * PH + h)) * PN * PHD;

    // Q fragments (pre-scaled), hi/lo, register-resident. 4 k16-steps.
    unsigned qh[4][4], ql[4][4];
    {
        const float* Qg = g_q + head_base + (size_t)(qt * 64 + w * 16) * PHD;
#pragma unroll
        for (int ks = 0; ks < 4; ks++) {
            int d = ks * 16 + 2 * tq;
            float2 v0 = *(const float2*)(Qg + (size_t)g * PHD + d);
            float2 v1 = *(const float2*)(Qg + (size_t)(g + 8) * PHD + d);
            float2 v2 = *(const float2*)(Qg + (size_t)g * PHD + d + 8);
            float2 v3 = *(const float2*)(Qg + (size_t)(g + 8) * PHD + d + 8);
            split2(v0.x * PSCALE, v0.y * PSCALE, qh[ks][0], ql[ks][0]);
            split2(v1.x * PSCALE, v1.y * PSCALE, qh[ks][1], ql[ks][1]);
            split2(v2.x * PSCALE, v2.y * PSCALE, qh[ks][2], ql[ks][2]);
            split2(v3.x * PSCALE, v3.y * PSCALE, qh[ks][3], ql[ks][3]);
        }
    }

    float o[8][4];
#pragma unroll
    for (int nt = 0; nt < 8; nt++)
#pragma unroll
        for (int c = 0; c < 4; c++) o[nt][c] = 0.f;
    float m0v = -1e30f, m1v = -1e30f;
    float l0 = 0.f, l1 = 0.f;

    const int vkq = lane & 3;
    const int vdq = lane >> 2;
    const int vd0 = 2 * vdq + 16 * w;

    float4 kR[8];                     // K prefetch (this thread's 8 float4s)
    float2 vR[8][2];                  // V prefetch

    auto ldg_kv = [&](int kt) {
        const float4* Kg = (const float4*)(g_k + head_base + (size_t)kt * 64 * PHD);
#pragma unroll
        for (int i = 0; i < 8; i++) kR[i] = Kg[t + i * 128];
        const float* Vg = g_v + head_base + (size_t)kt * 64 * PHD;
#pragma unroll
        for (int i = 0; i < 8; i++) {
            int kp = vkq + 4 * i;
            vR[i][0] = *(const float2*)(Vg + (size_t)(2 * kp) * PHD + vd0);
            vR[i][1] = *(const float2*)(Vg + (size_t)(2 * kp + 1) * PHD + vd0);
        }
    };

    auto store_kv = [&]() {
#pragma unroll
        for (int i = 0; i < 8; i++) {
            int idx = t + i * 128;
            int row = idx >> 4;
            int dp0 = (idx & 15) * 2;
            unsigned h0, lo0, h1, lo1;
            split2(kR[i].x, kR[i].y, h0, lo0);
            split2(kR[i].z, kR[i].w, h1, lo1);
            uint2 ph; ph.x = h0; ph.y = h1;
            uint2 pl; pl.x = lo0; pl.y = lo1;
            *(uint2*)&Kh[row][dp0] = ph;
            *(uint2*)&Kl[row][dp0] = pl;
        }
#pragma unroll
        for (int i = 0; i < 8; i++) {
            int kp = vkq + 4 * i;
            unsigned hA, lA, hB, lB;
            split2(vR[i][0].x, vR[i][1].x, hA, lA);
            split2(vR[i][0].y, vR[i][1].y, hB, lB);
            Vh[vd0][kp] = hA;     Vl[vd0][kp] = lA;
            Vh[vd0 + 1][kp] = hB; Vl[vd0 + 1][kp] = lB;
        }
    };

    ldg_kv(0);    // prologue prefetch

    for (int kt = 0; kt < PN / 64; kt++) {
        store_kv();
        __syncthreads();
        if (kt + 1 < PN / 64) ldg_kv(kt + 1);   // hidden under MMAs/softmax

        // S = Q @ K^T (3-MMA compensated), 16 rows x 64 keys
        float s[8][4];
#pragma unroll
        for (int nt = 0; nt < 8; nt++)
#pragma unroll
            for (int c = 0; c < 4; c++) s[nt][c] = 0.f;

#pragma unroll
        for (int nt = 0; nt < 8; nt++) {
            int key = nt * 8 + g;
#pragma unroll
            for (int ks = 0; ks < 4; ks++) {
                unsigned bh[2], bl[2];
                bh[0] = Kh[key][ks * 8 + tq];     bl[0] = Kl[key][ks * 8 + tq];
                bh[1] = Kh[key][ks * 8 + tq + 4]; bl[1] = Kl[key][ks * 8 + tq + 4];
                mma16(s[nt], qh[ks], bh);
                mma16(s[nt], ql[ks], bh);
                mma16(s[nt], qh[ks], bl);
            }
        }

        // Online softmax (rows r0 = w*16+g, r1 = r0+8)
        float tmax0 = -1e30f, tmax1 = -1e30f;
#pragma unroll
        for (int nt = 0; nt < 8; nt++) {
            tmax0 = fmaxf(tmax0, fmaxf(s[nt][0], s[nt][1]));
            tmax1 = fmaxf(tmax1, fmaxf(s[nt][2], s[nt][3]));
        }
        tmax0 = fmaxf(tmax0, __shfl_xor_sync(0xffffffffu, tmax0, 1));
        tmax0 = fmaxf(tmax0, __shfl_xor_sync(0xffffffffu, tmax0, 2));
        tmax1 = fmaxf(tmax1, __shfl_xor_sync(0xffffffffu, tmax1, 1));
        tmax1 = fmaxf(tmax1, __shfl_xor_sync(0xffffffffu, tmax1, 2));

        float mnew0 = fmaxf(m0v, tmax0);
        float mnew1 = fmaxf(m1v, tmax1);
        float corr0 = __expf(m0v - mnew0);
        float corr1 = __expf(m1v - mnew1);
#pragma unroll
        for (int nt = 0; nt < 8; nt++) {
            o[nt][0] *= corr0; o[nt][1] *= corr0;
            o[nt][2] *= corr1; o[nt][3] *= corr1;
        }

        float rs0 = 0.f, rs1 = 0.f;
#pragma unroll
        for (int nt = 0; nt < 8; nt++) {
            s[nt][0] = __expf(s[nt][0] - mnew0);
            s[nt][1] = __expf(s[nt][1] - mnew0);
            s[nt][2] = __expf(s[nt][2] - mnew1);
            s[nt][3] = __expf(s[nt][3] - mnew1);
            rs0 += s[nt][0] + s[nt][1];
            rs1 += s[nt][2] + s[nt][3];
        }
        rs0 += __shfl_xor_sync(0xffffffffu, rs0, 1);
        rs0 += __shfl_xor_sync(0xffffffffu, rs0, 2);
        rs1 += __shfl_xor_sync(0xffffffffu, rs1, 1);
        rs1 += __shfl_xor_sync(0xffffffffu, rs1, 2);
        l0 = l0 * corr0 + rs0;
        l1 = l1 * corr1 + rs1;
        m0v = mnew0;
        m1v = mnew1;

        // O += P @ V. P frags straight from s registers.
#pragma unroll
        for (int ks = 0; ks < 4; ks++) {
            unsigned ah[4], al[4];
            split2(s[2 * ks][0],     s[2 * ks][1],     ah[0], al[0]);
            split2(s[2 * ks][2],     s[2 * ks][3],     ah[1], al[1]);
            split2(s[2 * ks + 1][0], s[2 * ks + 1][1], ah[2], al[2]);
            split2(s[2 * ks + 1][2], s[2 * ks + 1][3], ah[3], al[3]);
#pragma unroll
            for (int nt = 0; nt < 8; nt++) {
                int dcol = nt * 8 + g;
                unsigned bh[2], bl[2];
                bh[0] = Vh[dcol][ks * 8 + tq];     bl[0] = Vl[dcol][ks * 8 + tq];
                bh[1] = Vh[dcol][ks * 8 + tq + 4]; bl[1] = Vl[dcol][ks * 8 + tq + 4];
                mma16(o[nt], ah, bh);
                mma16(o[nt], al, bh);
                mma16(o[nt], ah, bl);
            }
        }
        __syncthreads();   // all reads done before next store_kv overwrites
    }

    // Normalize and write ctx in [B*N, D] layout
    float inv0 = 1.f / l0;
    float inv1 = 1.f / l1;
    float* Og0 = g_ctx + ((size_t)(b * PN) + qt * 64 + w * 16 + g) * PD + h * PHD;
    float* Og1 = Og0 + (size_t)8 * PD;
#pragma unroll
    for (int nt = 0; nt < 8; nt++) {
        int col = nt * 8 + 2 * tq;
        float2 lo; lo.x = o[nt][0] * inv0; lo.y = o[nt][1] * inv0;
        float2 hi; hi.x = o[nt][2] * inv1; hi.y = o[nt][3] * inv1;
        *(float2*)(Og0 + col) = lo;
        *(float2*)(Og1 + col) = hi;
    }
}

// ---------------------------------------------------------------------------
extern "C" void kernel_launch(void* const* d_in, const int* in_sizes, int n_in,
                              void* d_out, int out_size)
{
    const float* x      = (const float*)d_in[0];
    const float* w_qkv  = (const float*)d_in[1];
    const float* b_qkv  = (const float*)d_in[2];
    const float* w_proj = (const float*)d_in[3];
    const float* b_proj = (const float*)d_in[4];
    float* out = (float*)d_out;

    (void)in_sizes; (void)n_in; (void)out_size;

    // Opt in to >48KB dynamic SMEM (idempotent; host-side, not a graph node)
    static bool attr_done = false;
    if (!attr_done) {
        cudaFuncSetAttribute((const void*)gemm_tc<0>,
                             cudaFuncAttributeMaxDynamicSharedMemorySize, GEMM_SMEM_BYTES);
        cudaFuncSetAttribute((const void*)gemm_tc<1>,
                             cudaFuncAttributeMaxDynamicSharedMemorySize, GEMM_SMEM_BYTES);
        attr_done = true;
    }

    // 1) QKV projection: [8192,768] @ [768,2304] -> scattered Q/K/V
    dim3 g1(PQKV / 128, PM / 128);               // (18, 64)
    gemm_tc<0><<<g1, 256, GEMM_SMEM_BYTES>>>(x, w_qkv, b_qkv, nullptr, PD, PQKV);

    // 2) Attention per (q-tile, head, batch)
    attn_tc<<<dim3(PN / 64, PH, PB), 128>>>();

    // 3) Output projection: [8192,768] @ [768,768] + bias -> d_out
    dim3 g3(PD / 128, PM / 128);                 // (6, 64)
    gemm_tc<1><<<g3, 256, GEMM_SMEM_BYTES>>>(nullptr, w_proj, b_proj, out, PD, PD);
}